// round 14
// baseline (speedup 1.0000x reference)
#include <cuda_runtime.h>
#include <cuda_bf16.h>
#include <cstdint>

#define NEXP    256
#define CAP     128
#define N_ROWS  16384
#define THREADS 256

// smem byte offsets
#define HHI   0         // h hi [64][256] bf16, stride 512B (32 KB)
#define HLO   32768     // h lo (32 KB)
#define XHI   65536     // x hi [64][64] bf16, stride 128B (8 KB)
#define XLO   73728     // x lo (8 KB)
#define WBUF  81920     // 2 chunk bufs x 16 KB (hi 8K + lo 8K each); W3 phase: hi 16K @WBUF, lo 16K @+16384
#define SMEM_TOTAL 114688

__device__ int g_cnt[NEXP];
__device__ int g_bucket[NEXP * CAP];

// ---------------- grouping ----------------
__global__ void k_fill(const int* __restrict__ ind) {
    int i = blockIdx.x * blockDim.x + threadIdx.x;
    int e = ind[i];
    int p = atomicAdd(&g_cnt[e], 1);
    if (p < CAP) g_bucket[e * CAP + p] = i;
}

// ---------------- helpers ----------------
__device__ __forceinline__ uint32_t smem_u32(const void* p) {
    uint32_t a;
    asm("{ .reg .u64 t; cvta.to.shared.u64 t, %1; cvt.u32.u64 %0, t; }" : "=r"(a) : "l"(p));
    return a;
}
__device__ __forceinline__ void ldm4(uint32_t* r, uint32_t a) {
    asm volatile("ldmatrix.sync.aligned.m8n8.x4.shared.b16 {%0,%1,%2,%3}, [%4];"
        : "=r"(r[0]), "=r"(r[1]), "=r"(r[2]), "=r"(r[3]) : "r"(a));
}
__device__ __forceinline__ void mma16816(float* d, const uint32_t* a, const uint32_t* b) {
    asm volatile("mma.sync.aligned.m16n8k16.row.col.f32.bf16.bf16.f32 "
        "{%0,%1,%2,%3}, {%4,%5,%6,%7}, {%8,%9}, {%0,%1,%2,%3};"
        : "+f"(d[0]), "+f"(d[1]), "+f"(d[2]), "+f"(d[3])
        : "r"(a[0]), "r"(a[1]), "r"(a[2]), "r"(a[3]), "r"(b[0]), "r"(b[1]));
}
__device__ __forceinline__ float fast_tanh(float x) {
    float ax = fabsf(x);
    float t = __expf(-2.0f * ax);
    float r = __fdividef(1.0f - t, 1.0f + t);
    return copysignf(r, x);
}
__device__ __forceinline__ uint32_t bpackr(float x, float y, float& rx, float& ry) {
    __nv_bfloat16 hx = __float2bfloat16_rn(x), hy = __float2bfloat16_rn(y);
    rx = x - __bfloat162float(hx);
    ry = y - __bfloat162float(hy);
    return (uint32_t)__bfloat16_as_ushort(hx) | ((uint32_t)__bfloat16_as_ushort(hy) << 16);
}
__device__ __forceinline__ uint32_t bpack(float x, float y) {
    return (uint32_t)__bfloat16_as_ushort(__float2bfloat16_rn(x)) |
           ((uint32_t)__bfloat16_as_ushort(__float2bfloat16_rn(y)) << 16);
}
__device__ __forceinline__ void split8(float4 a, float4 b, uint4& hi, uint4& lo) {
    float r0, r1, r2, r3, r4, r5, r6, r7;
    hi.x = bpackr(a.x, a.y, r0, r1);
    hi.y = bpackr(a.z, a.w, r2, r3);
    hi.z = bpackr(b.x, b.y, r4, r5);
    hi.w = bpackr(b.z, b.w, r6, r7);
    lo.x = bpack(r0, r1); lo.y = bpack(r2, r3);
    lo.z = bpack(r4, r5); lo.w = bpack(r6, r7);
}

// swizzled byte offsets (conflict-free for ldmatrix phases & STS patterns)
__device__ __forceinline__ uint32_t aoff(int m, int kb)    { return m * 512 + (kb ^ ((m & 7) << 4)); }
__device__ __forceinline__ uint32_t xoff(int m, int kb)    { return m * 128 + (kb ^ ((m & 7) << 4)); }
__device__ __forceinline__ uint32_t woff16(int o, int kb)  { return o * 32  + (kb ^ (((o >> 2) & 1) << 4)); }
__device__ __forceinline__ uint32_t woff3p(int o, int kb)  { return o * 256 + (kb ^ ((o & 7) << 4)); }

extern __shared__ char smc[];

// store one 16-float (16-k) weight slice (hi/lo split) into a chunk buffer [256 o][16 k]
__device__ __forceinline__ void sts_chunk16(uint32_t bufOff, int o, const float4* pf) {
    uint4 h0, h1, l0, l1;
    split8(pf[0], pf[1], h0, l0);
    split8(pf[2], pf[3], h1, l1);
    *(uint4*)(smc + bufOff + woff16(o, 0))         = h0;
    *(uint4*)(smc + bufOff + woff16(o, 16))        = h1;
    *(uint4*)(smc + bufOff + 8192 + woff16(o, 0))  = l0;
    *(uint4*)(smc + bufOff + 8192 + woff16(o, 16)) = l1;
}

__global__ __launch_bounds__(THREADS, 2)
void k_mlp(const float* __restrict__ Xg,
           const float* __restrict__ W1, const float* __restrict__ B1,
           const float* __restrict__ W2, const float* __restrict__ B2,
           const float* __restrict__ W3, const float* __restrict__ B3,
           float* __restrict__ Og) {
    int e = blockIdx.x;
    int cnt = min(g_cnt[e], CAP);
    int rs = (int)blockIdx.y * 64;
    if (rs >= cnt) return;
    int mrows = min(64, cnt - rs);

    int tid = threadIdx.x;
    int lane = tid & 31, wid = tid >> 5;
    int rg = wid >> 1, ch = wid & 1;       // 4 row groups x 2 col halves
    int m0 = rg * 16;
    bool act = (m0 < mrows);
    uint32_t sb = smem_u32(smc);

    // ldmatrix lane address components
    int aRow = lane & 15;
    int aK = (lane >> 4) << 4;
    int bO = (lane & 7) | ((lane >> 4) << 3);
    int bK = ((lane >> 3) & 1) << 4;

    // ---- stage x (hi/lo, swizzled), zero-pad ----
    {
        int m = tid >> 2, kq = (tid & 3) * 16;
        float4 v[4];
        if (m < mrows) {
            int n = g_bucket[e * CAP + rs + m];
            const float4* src = (const float4*)(Xg + (size_t)n * 64 + kq);
            #pragma unroll
            for (int j = 0; j < 4; j++) v[j] = src[j];
        } else {
            #pragma unroll
            for (int j = 0; j < 4; j++) v[j] = make_float4(0.f, 0.f, 0.f, 0.f);
        }
        uint4 h0, h1, l0, l1;
        split8(v[0], v[1], h0, l0);
        split8(v[2], v[3], h1, l1);
        int kb = kq * 2;
        *(uint4*)(smc + XHI + xoff(m, kb))      = h0;
        *(uint4*)(smc + XHI + xoff(m, kb + 16)) = h1;
        *(uint4*)(smc + XLO + xoff(m, kb))      = l0;
        *(uint4*)(smc + XLO + xoff(m, kb + 16)) = l1;
    }
    // ---- stage W1 chunk 0 -> buf0 ----
    const float* w1t = W1 + (size_t)e * 16384 + tid * 64;     // [256 o][64 k]
    const float* w2t = W2 + (size_t)e * 65536 + tid * 256;    // [256 o][256 k]
    float4 pf[4];
    {
        #pragma unroll
        for (int j = 0; j < 4; j++) pf[j] = *(const float4*)(w1t + j * 4);
        sts_chunk16(WBUF, tid, pf);
    }
    __syncthreads();

    float acc[64];
    #pragma unroll
    for (int i = 0; i < 64; i++) acc[i] = 0.f;

    // ---- layer 1: 64 -> 256, 4 chunks of 16 k ----
    #pragma unroll 1
    for (int c = 0; c < 4; c++) {
        const float* nsrc = (c < 3) ? (w1t + (c + 1) * 16) : w2t;
        #pragma unroll
        for (int j = 0; j < 4; j++) pf[j] = *(const float4*)(nsrc + j * 4);

        if (act) {
            uint32_t bufH = sb + WBUF + (c & 1) * 16384;
            uint32_t aaddr = sb + XHI + xoff(m0 + aRow, c * 32 + aK);
            uint32_t ah[4], al[4];
            ldm4(ah, aaddr);
            ldm4(al, aaddr + (XLO - XHI));
            #pragma unroll
            for (int np = 0; np < 8; np++) {
                int n0 = ch * 128 + np * 16;
                uint32_t baddr = bufH + woff16(n0 + bO, bK);
                uint32_t bh[4], bl[4];
                ldm4(bh, baddr);
                ldm4(bl, baddr + 8192);
                float* A0 = acc + np * 8;
                mma16816(A0, ah, bh);
                mma16816(A0, ah, bl);
                mma16816(A0, al, bh);
                mma16816(A0 + 4, ah, bh + 2);
                mma16816(A0 + 4, ah, bl + 2);
                mma16816(A0 + 4, al, bh + 2);
            }
        }
        if (c == 3 && act) {
            // epilogue 1: + bias, tanh, split -> h
            const float* bg = B1 + (size_t)e * 256;
            int r0 = m0 + (lane >> 2);
            #pragma unroll
            for (int t = 0; t < 16; t++) {
                int c0 = ch * 128 + t * 8 + (lane & 3) * 2;
                float2 bv = *(const float2*)(bg + c0);
                float v0 = fast_tanh(acc[t * 4 + 0] + bv.x);
                float v1 = fast_tanh(acc[t * 4 + 1] + bv.y);
                float v2 = fast_tanh(acc[t * 4 + 2] + bv.x);
                float v3 = fast_tanh(acc[t * 4 + 3] + bv.y);
                float q0, q1, q2, q3;
                uint32_t h0 = bpackr(v0, v1, q0, q1), l0v = bpack(q0, q1);
                uint32_t h1 = bpackr(v2, v3, q2, q3), l1v = bpack(q2, q3);
                int kb = c0 * 2;
                *(uint32_t*)(smc + HHI + aoff(r0, kb))     = h0;
                *(uint32_t*)(smc + HLO + aoff(r0, kb))     = l0v;
                *(uint32_t*)(smc + HHI + aoff(r0 + 8, kb)) = h1;
                *(uint32_t*)(smc + HLO + aoff(r0 + 8, kb)) = l1v;
            }
        }
        sts_chunk16(WBUF + ((c + 1) & 1) * 16384, tid, pf);
        __syncthreads();
    }

    #pragma unroll
    for (int i = 0; i < 64; i++) acc[i] = 0.f;

    // ---- layer 2: 256 -> 256, 16 pipelined chunks of 16 k ----
    #pragma unroll 1
    for (int c = 0; c < 16; c++) {
        if (c < 15) {
            #pragma unroll
            for (int j = 0; j < 4; j++) pf[j] = *(const float4*)(w2t + (c + 1) * 16 + j * 4);
        }
        if (act) {
            uint32_t bufH = sb + WBUF + (c & 1) * 16384;
            uint32_t aaddr = sb + HHI + aoff(m0 + aRow, c * 32 + aK);
            uint32_t ah[4], al[4];
            ldm4(ah, aaddr);
            ldm4(al, aaddr + 32768);
            #pragma unroll
            for (int np = 0; np < 8; np++) {
                int n0 = ch * 128 + np * 16;
                uint32_t baddr = bufH + woff16(n0 + bO, bK);
                uint32_t bh[4], bl[4];
                ldm4(bh, baddr);
                ldm4(bl, baddr + 8192);
                float* A0 = acc + np * 8;
                mma16816(A0, ah, bh);
                mma16816(A0, ah, bl);
                mma16816(A0, al, bh);
                mma16816(A0 + 4, ah, bh + 2);
                mma16816(A0 + 4, ah, bl + 2);
                mma16816(A0 + 4, al, bh + 2);
            }
        }
        if (c < 15) sts_chunk16(WBUF + ((c + 1) & 1) * 16384, tid, pf);
        __syncthreads();
    }

    // ---- layer 3 setup: W3 in two 128-k phases through WBUF ----
    int o3 = tid >> 2, kq3 = (tid & 3) * 32;                  // [64 o][128 k] per phase
    const float* w3t = W3 + (size_t)e * 16384 + o3 * 256 + kq3;
    float4 p3[8];
    #pragma unroll
    for (int j = 0; j < 8; j++) p3[j] = *(const float4*)(w3t + j * 4);   // phase 0 (k 0..127)

    // epilogue 2: + bias, tanh, split -> h (overlaps W3 phase-0 LDG)
    if (act) {
        const float* bg = B2 + (size_t)e * 256;
        int r0 = m0 + (lane >> 2);
        #pragma unroll
        for (int t = 0; t < 16; t++) {
            int c0 = ch * 128 + t * 8 + (lane & 3) * 2;
            float2 bv = *(const float2*)(bg + c0);
            float v0 = fast_tanh(acc[t * 4 + 0] + bv.x);
            float v1 = fast_tanh(acc[t * 4 + 1] + bv.y);
            float v2 = fast_tanh(acc[t * 4 + 2] + bv.x);
            float v3 = fast_tanh(acc[t * 4 + 3] + bv.y);
            float q0, q1, q2, q3;
            uint32_t h0 = bpackr(v0, v1, q0, q1), l0v = bpack(q0, q1);
            uint32_t h1 = bpackr(v2, v3, q2, q3), l1v = bpack(q2, q3);
            int kb = c0 * 2;
            *(uint32_t*)(smc + HHI + aoff(r0, kb))     = h0;
            *(uint32_t*)(smc + HLO + aoff(r0, kb))     = l0v;
            *(uint32_t*)(smc + HHI + aoff(r0 + 8, kb)) = h1;
            *(uint32_t*)(smc + HLO + aoff(r0 + 8, kb)) = l1v;
        }
    }
    // STS W3 phase 0 -> WBUF (hi @0, lo @+16384)
    #pragma unroll
    for (int j = 0; j < 4; j++) {
        uint4 hi, lo;
        split8(p3[2 * j], p3[2 * j + 1], hi, lo);
        uint32_t kb = kq3 * 2 + j * 16;
        *(uint4*)(smc + WBUF + woff3p(o3, kb))         = hi;
        *(uint4*)(smc + WBUF + 16384 + woff3p(o3, kb)) = lo;
    }
    __syncthreads();

    // LDG W3 phase 1 (k 128..255)
    #pragma unroll
    for (int j = 0; j < 8; j++) p3[j] = *(const float4*)(w3t + 128 + j * 4);

    float acc3[16];
    #pragma unroll
    for (int i = 0; i < 16; i++) acc3[i] = 0.f;

    // ---- layer 3: two phases of 128 k ----
    #pragma unroll 1
    for (int ph = 0; ph < 2; ph++) {
        if (act) {
            #pragma unroll 4
            for (int kb16 = 0; kb16 < 8; kb16++) {
                int k0 = kb16 * 16;
                uint32_t aaddr = sb + HHI + aoff(m0 + aRow, (ph * 128 + k0) * 2 + aK);
                uint32_t ah[4], al[4];
                ldm4(ah, aaddr);
                ldm4(al, aaddr + 32768);
                #pragma unroll
                for (int np = 0; np < 2; np++) {
                    int n0 = ch * 32 + np * 16;
                    uint32_t baddr = sb + WBUF + woff3p(n0 + bO, k0 * 2 + bK);
                    uint32_t bh[4], bl[4];
                    ldm4(bh, baddr);
                    ldm4(bl, baddr + 16384);
                    float* A0 = acc3 + np * 8;
                    mma16816(A0, ah, bh);
                    mma16816(A0, ah, bl);
                    mma16816(A0, al, bh);
                    mma16816(A0 + 4, ah, bh + 2);
                    mma16816(A0 + 4, ah, bl + 2);
                    mma16816(A0 + 4, al, bh + 2);
                }
            }
        }
        if (ph == 0) {
            __syncthreads();   // phase-0 reads done
            #pragma unroll
            for (int j = 0; j < 4; j++) {
                uint4 hi, lo;
                split8(p3[2 * j], p3[2 * j + 1], hi, lo);
                uint32_t kb = kq3 * 2 + j * 16;
                *(uint4*)(smc + WBUF + woff3p(o3, kb))         = hi;
                *(uint4*)(smc + WBUF + 16384 + woff3p(o3, kb)) = lo;
            }
            __syncthreads();
        }
    }

    // ---- epilogue 3: + bias -> scatter ----
    if (act) {
        const float* bg = B3 + (size_t)e * 64;
        int r0 = m0 + (lane >> 2), r1 = r0 + 8;
        int n0g = (r0 < mrows) ? g_bucket[e * CAP + rs + r0] : -1;
        int n1g = (r1 < mrows) ? g_bucket[e * CAP + rs + r1] : -1;
        #pragma unroll
        for (int t = 0; t < 4; t++) {
            int c0 = ch * 32 + t * 8 + (lane & 3) * 2;
            float2 bv = *(const float2*)(bg + c0);
            if (n0g >= 0) {
                float2 o = make_float2(acc3[t * 4 + 0] + bv.x, acc3[t * 4 + 1] + bv.y);
                *(float2*)(Og + (size_t)n0g * 64 + c0) = o;
            }
            if (n1g >= 0) {
                float2 o = make_float2(acc3[t * 4 + 2] + bv.x, acc3[t * 4 + 3] + bv.y);
                *(float2*)(Og + (size_t)n1g * 64 + c0) = o;
            }
        }
    }
}

// ---------------- launch ----------------
extern "C" void kernel_launch(void* const* d_in, const int* in_sizes, int n_in,
                              void* d_out, int out_size) {
    const float* x  = (const float*)d_in[0];
    const int*   ind = (const int*)d_in[1];
    const float* W1 = (const float*)d_in[2];
    const float* b1 = (const float*)d_in[3];
    const float* W2 = (const float*)d_in[4];
    const float* b2 = (const float*)d_in[5];
    const float* Wl = (const float*)d_in[6];
    const float* bl = (const float*)d_in[7];
    float* out = (float*)d_out;

    (void)in_sizes; (void)n_in; (void)out_size;

    cudaFuncSetAttribute(k_mlp, cudaFuncAttributeMaxDynamicSharedMemorySize, SMEM_TOTAL);

    void* cnt_ptr = nullptr;
    cudaGetSymbolAddress(&cnt_ptr, g_cnt);
    cudaMemsetAsync(cnt_ptr, 0, NEXP * sizeof(int));

    k_fill<<<N_ROWS / 256, 256>>>(ind);
    k_mlp<<<dim3(NEXP, 2), THREADS, SMEM_TOTAL>>>(x, W1, b1, W2, b2, Wl, bl, out);
}

// round 17
// speedup vs baseline: 1.1287x; 1.1287x over previous
#include <cuda_runtime.h>
#include <cuda_bf16.h>
#include <cstdint>

#define NEXP    256
#define CAP     128
#define N_ROWS  16384
#define THREADS 512

// smem byte offsets
#define HHI   0         // h hi  [128][256] bf16, stride 512B
#define HLO   65536     // h lo
#define WBUF  131072    // 64KB: 2 chunk bufs (hi 16K + lo 16K each); also W3 (hi 32K @WBUF, lo 32K @+32768)
#define XHI   196608    // x hi [128][64] bf16, stride 128B
#define XLO   212992
#define SMEM_TOTAL 229376

__device__ int g_cnt[NEXP];
__device__ int g_bucket[NEXP * CAP];

// ---------------- grouping ----------------
__global__ void k_fill(const int* __restrict__ ind) {
    int i = blockIdx.x * blockDim.x + threadIdx.x;
    int e = ind[i];
    int p = atomicAdd(&g_cnt[e], 1);
    if (p < CAP) g_bucket[e * CAP + p] = i;
}

// ---------------- helpers ----------------
__device__ __forceinline__ uint32_t smem_u32(const void* p) {
    uint32_t a;
    asm("{ .reg .u64 t; cvta.to.shared.u64 t, %1; cvt.u32.u64 %0, t; }" : "=r"(a) : "l"(p));
    return a;
}
__device__ __forceinline__ void ldm4(uint32_t* r, uint32_t a) {
    asm volatile("ldmatrix.sync.aligned.m8n8.x4.shared.b16 {%0,%1,%2,%3}, [%4];"
        : "=r"(r[0]), "=r"(r[1]), "=r"(r[2]), "=r"(r[3]) : "r"(a));
}
__device__ __forceinline__ void mma16816(float* d, const uint32_t* a, const uint32_t* b) {
    asm volatile("mma.sync.aligned.m16n8k16.row.col.f32.bf16.bf16.f32 "
        "{%0,%1,%2,%3}, {%4,%5,%6,%7}, {%8,%9}, {%0,%1,%2,%3};"
        : "+f"(d[0]), "+f"(d[1]), "+f"(d[2]), "+f"(d[3])
        : "r"(a[0]), "r"(a[1]), "r"(a[2]), "r"(a[3]), "r"(b[0]), "r"(b[1]));
}
__device__ __forceinline__ float fast_tanh(float x) {
    float ax = fabsf(x);
    float t = __expf(-2.0f * ax);
    float r = __fdividef(1.0f - t, 1.0f + t);
    return copysignf(r, x);
}
__device__ __forceinline__ uint32_t bpackr(float x, float y, float& rx, float& ry) {
    __nv_bfloat16 hx = __float2bfloat16_rn(x), hy = __float2bfloat16_rn(y);
    rx = x - __bfloat162float(hx);
    ry = y - __bfloat162float(hy);
    return (uint32_t)__bfloat16_as_ushort(hx) | ((uint32_t)__bfloat16_as_ushort(hy) << 16);
}
__device__ __forceinline__ uint32_t bpack(float x, float y) {
    return (uint32_t)__bfloat16_as_ushort(__float2bfloat16_rn(x)) |
           ((uint32_t)__bfloat16_as_ushort(__float2bfloat16_rn(y)) << 16);
}
__device__ __forceinline__ void split8(float4 a, float4 b, uint4& hi, uint4& lo) {
    float r0, r1, r2, r3, r4, r5, r6, r7;
    hi.x = bpackr(a.x, a.y, r0, r1);
    hi.y = bpackr(a.z, a.w, r2, r3);
    hi.z = bpackr(b.x, b.y, r4, r5);
    hi.w = bpackr(b.z, b.w, r6, r7);
    lo.x = bpack(r0, r1); lo.y = bpack(r2, r3);
    lo.z = bpack(r4, r5); lo.w = bpack(r6, r7);
}

// swizzled byte offsets (conflict-free for ldmatrix & STS patterns)
__device__ __forceinline__ uint32_t aoff(int m, int kb)  { return m * 512 + (kb ^ ((m & 7) << 4)); }
__device__ __forceinline__ uint32_t xoff(int m, int kb)  { return m * 128 + (kb ^ ((m & 7) << 4)); }
__device__ __forceinline__ uint32_t woff(int o, int kb)  { return o * 64  + (kb ^ (((o >> 1) & 3) << 4)); }
__device__ __forceinline__ uint32_t woff3(int o, int kb) { return o * 512 + (kb ^ ((o & 7) << 4)); }

extern __shared__ char smc[];

// store one 16-float weight slice (hi/lo split) into a chunk buffer [256 o][32 k]
__device__ __forceinline__ void sts_chunk(uint32_t bufOff, int o, int khB, const float4* pf) {
    uint4 h0, h1, l0, l1;
    split8(pf[0], pf[1], h0, l0);
    split8(pf[2], pf[3], h1, l1);
    *(uint4*)(smc + bufOff + woff(o, khB))           = h0;
    *(uint4*)(smc + bufOff + woff(o, khB + 16))      = h1;
    *(uint4*)(smc + bufOff + 16384 + woff(o, khB))      = l0;
    *(uint4*)(smc + bufOff + 16384 + woff(o, khB + 16)) = l1;
}

__global__ __launch_bounds__(THREADS, 1)
void k_mlp(const float* __restrict__ Xg,
           const float* __restrict__ W1, const float* __restrict__ B1,
           const float* __restrict__ W2, const float* __restrict__ B2,
           const float* __restrict__ W3, const float* __restrict__ B3,
           float* __restrict__ Og) {
    int e = blockIdx.x;
    int mrows = min(g_cnt[e], CAP);
    if (mrows == 0) return;
    int npass = (mrows + 63) >> 6;       // 1 or 2 row-passes of 64

    int tid = threadIdx.x;
    int lane = tid & 31, wid = tid >> 5;
    int rg = wid & 3, ch = wid >> 2;     // 4 row groups x 4 col quarters
    int m0p = rg * 16;                   // row offset within a pass
    uint32_t sb = smem_u32(smc);

    // ldmatrix lane address components
    int aRow = lane & 15;
    int aK = (lane >> 4) << 4;
    int bO = (lane & 7) | ((lane >> 4) << 3);
    int bK = ((lane >> 3) & 1) << 4;

    // ---- stage x (hi/lo, swizzled), zero-pad to 128 rows ----
    {
        int m = tid >> 2, kq = (tid & 3) * 16;
        float4 v[4];
        if (m < mrows) {
            int n = g_bucket[e * CAP + m];
            const float4* src = (const float4*)(Xg + (size_t)n * 64 + kq);
            #pragma unroll
            for (int j = 0; j < 4; j++) v[j] = src[j];
        } else {
            #pragma unroll
            for (int j = 0; j < 4; j++) v[j] = make_float4(0.f, 0.f, 0.f, 0.f);
        }
        uint4 h0, h1, l0, l1;
        split8(v[0], v[1], h0, l0);
        split8(v[2], v[3], h1, l1);
        int kb = kq * 2;
        *(uint4*)(smc + XHI + xoff(m, kb))      = h0;
        *(uint4*)(smc + XHI + xoff(m, kb + 16)) = h1;
        *(uint4*)(smc + XLO + xoff(m, kb))      = l0;
        *(uint4*)(smc + XLO + xoff(m, kb + 16)) = l1;
    }
    // ---- stage W1: chunk0 -> buf0, chunk1 -> buf1 ----
    int so = tid >> 1;
    int skh = (tid & 1) * 16;
    int skhB = skh * 2;
    {
        #pragma unroll
        for (int c = 0; c < 2; c++) {
            const float* src = W1 + (size_t)e * 16384 + so * 64 + c * 32 + skh;
            float4 v[4];
            #pragma unroll
            for (int j = 0; j < 4; j++) v[j] = *(const float4*)(src + j * 4);
            sts_chunk(WBUF + c * 32768, so, skhB, v);
        }
    }
    __syncthreads();

    float acc[2][32];
    #pragma unroll
    for (int p = 0; p < 2; p++)
        #pragma unroll
        for (int i = 0; i < 32; i++) acc[p][i] = 0.f;

    // ---- layer 1: 64 -> 256 ----
    #pragma unroll
    for (int kb4 = 0; kb4 < 4; kb4++) {
        uint32_t bufH = sb + WBUF + (kb4 >> 1) * 32768;
        #pragma unroll
        for (int p = 0; p < 2; p++) {
            if (p < npass) {
                uint32_t aaddr = sb + XHI + xoff(p * 64 + m0p + aRow, kb4 * 32 + aK);
                uint32_t ah[4], al[4];
                ldm4(ah, aaddr);
                ldm4(al, aaddr + (XLO - XHI));
                #pragma unroll
                for (int np = 0; np < 4; np++) {
                    int n0 = ch * 64 + np * 16;
                    uint32_t baddr = bufH + woff(n0 + bO, (kb4 & 1) * 32 + bK);
                    uint32_t bh[4], bl[4];
                    ldm4(bh, baddr);
                    ldm4(bl, baddr + 16384);
                    float* A0 = acc[p] + np * 8;
                    mma16816(A0, ah, bh);
                    mma16816(A0, ah, bl);
                    mma16816(A0, al, bh);
                    mma16816(A0 + 4, ah, bh + 2);
                    mma16816(A0 + 4, ah, bl + 2);
                    mma16816(A0 + 4, al, bh + 2);
                }
            }
        }
    }

    // prefetch W2 chunk 0
    const float* w2t = W2 + (size_t)e * 65536 + so * 256 + skh;
    float4 pf[4];
    #pragma unroll
    for (int j = 0; j < 4; j++) pf[j] = *(const float4*)(w2t + j * 4);

    // epilogue 1: + bias, tanh, split -> h
    {
        const float* bg = B1 + (size_t)e * 256;
        #pragma unroll
        for (int p = 0; p < 2; p++) {
            if (p < npass) {
                int r0 = p * 64 + m0p + (lane >> 2);
                #pragma unroll
                for (int t = 0; t < 8; t++) {
                    int c0 = ch * 64 + t * 8 + (lane & 3) * 2;
                    float2 bv = *(const float2*)(bg + c0);
                    float v0 = fast_tanh(acc[p][t * 4 + 0] + bv.x);
                    float v1 = fast_tanh(acc[p][t * 4 + 1] + bv.y);
                    float v2 = fast_tanh(acc[p][t * 4 + 2] + bv.x);
                    float v3 = fast_tanh(acc[p][t * 4 + 3] + bv.y);
                    float q0, q1, q2, q3;
                    uint32_t h0 = bpackr(v0, v1, q0, q1), l0v = bpack(q0, q1);
                    uint32_t h1 = bpackr(v2, v3, q2, q3), l1v = bpack(q2, q3);
                    int kb = c0 * 2;
                    *(uint32_t*)(smc + HHI + aoff(r0, kb))     = h0;
                    *(uint32_t*)(smc + HLO + aoff(r0, kb))     = l0v;
                    *(uint32_t*)(smc + HHI + aoff(r0 + 8, kb)) = h1;
                    *(uint32_t*)(smc + HLO + aoff(r0 + 8, kb)) = l1v;
                }
            }
        }
    }
    __syncthreads();           // all L1 mma reads of bufs done
    sts_chunk(WBUF, so, skhB, pf);
    __syncthreads();

    #pragma unroll
    for (int p = 0; p < 2; p++)
        #pragma unroll
        for (int i = 0; i < 32; i++) acc[p][i] = 0.f;

    // ---- layer 2: 256 -> 256, 8 pipelined 32-k chunks ----
    #pragma unroll 1
    for (int c = 0; c < 8; c++) {
        if (c < 7) {
            #pragma unroll
            for (int j = 0; j < 4; j++) pf[j] = *(const float4*)(w2t + (c + 1) * 32 + j * 4);
        }
        uint32_t bufH = sb + WBUF + (c & 1) * 32768;
        #pragma unroll
        for (int kk = 0; kk < 2; kk++) {
            #pragma unroll
            for (int p = 0; p < 2; p++) {
                if (p < npass) {
                    uint32_t aaddr = sb + HHI + aoff(p * 64 + m0p + aRow, c * 64 + kk * 32 + aK);
                    uint32_t ah[4], al[4];
                    ldm4(ah, aaddr);
                    ldm4(al, aaddr + 65536);
                    #pragma unroll
                    for (int np = 0; np < 4; np++) {
                        int n0 = ch * 64 + np * 16;
                        uint32_t baddr = bufH + woff(n0 + bO, kk * 32 + bK);
                        uint32_t bh[4], bl[4];
                        ldm4(bh, baddr);
                        ldm4(bl, baddr + 16384);
                        float* A0 = acc[p] + np * 8;
                        mma16816(A0, ah, bh);
                        mma16816(A0, ah, bl);
                        mma16816(A0, al, bh);
                        mma16816(A0 + 4, ah, bh + 2);
                        mma16816(A0 + 4, ah, bl + 2);
                        mma16816(A0 + 4, al, bh + 2);
                    }
                }
            }
        }
        if (c < 7) sts_chunk(WBUF + ((c + 1) & 1) * 32768, so, skhB, pf);
        __syncthreads();
    }

    // ---- W3 LDG + epilogue 2 (overlapped) ----
    int o3 = tid >> 3, kq3 = (tid & 7) * 32;
    const float* w3t = W3 + (size_t)e * 16384 + o3 * 256 + kq3;
    float4 p3[8];
    #pragma unroll
    for (int j = 0; j < 8; j++) p3[j] = *(const float4*)(w3t + j * 4);

    {
        const float* bg = B2 + (size_t)e * 256;
        #pragma unroll
        for (int p = 0; p < 2; p++) {
            if (p < npass) {
                int r0 = p * 64 + m0p + (lane >> 2);
                #pragma unroll
                for (int t = 0; t < 8; t++) {
                    int c0 = ch * 64 + t * 8 + (lane & 3) * 2;
                    float2 bv = *(const float2*)(bg + c0);
                    float v0 = fast_tanh(acc[p][t * 4 + 0] + bv.x);
                    float v1 = fast_tanh(acc[p][t * 4 + 1] + bv.y);
                    float v2 = fast_tanh(acc[p][t * 4 + 2] + bv.x);
                    float v3 = fast_tanh(acc[p][t * 4 + 3] + bv.y);
                    float q0, q1, q2, q3;
                    uint32_t h0 = bpackr(v0, v1, q0, q1), l0v = bpack(q0, q1);
                    uint32_t h1 = bpackr(v2, v3, q2, q3), l1v = bpack(q2, q3);
                    int kb = c0 * 2;
                    *(uint32_t*)(smc + HHI + aoff(r0, kb))     = h0;
                    *(uint32_t*)(smc + HLO + aoff(r0, kb))     = l0v;
                    *(uint32_t*)(smc + HHI + aoff(r0 + 8, kb)) = h1;
                    *(uint32_t*)(smc + HLO + aoff(r0 + 8, kb)) = l1v;
                }
            }
        }
    }
    // stage W3 -> WBUF region ([64][256], hi @WBUF, lo @+32768)
    {
        #pragma unroll
        for (int j = 0; j < 4; j++) {
            uint4 hi, lo;
            split8(p3[2 * j], p3[2 * j + 1], hi, lo);
            uint32_t kb = kq3 * 2 + j * 16;
            *(uint4*)(smc + WBUF + woff3(o3, kb))         = hi;
            *(uint4*)(smc + WBUF + 32768 + woff3(o3, kb)) = lo;
        }
    }
    __syncthreads();

    // ---- layer 3: 256 -> 64 ----
    float acc3[2][8];
    #pragma unroll
    for (int p = 0; p < 2; p++)
        #pragma unroll
        for (int i = 0; i < 8; i++) acc3[p][i] = 0.f;

    #pragma unroll 2
    for (int kb16 = 0; kb16 < 16; kb16++) {
        int k0 = kb16 * 16;
        int n0 = ch * 16;
        uint32_t baddr = sb + WBUF + woff3(n0 + bO, k0 * 2 + bK);
        uint32_t bh[4], bl[4];
        ldm4(bh, baddr);
        ldm4(bl, baddr + 32768);
        #pragma unroll
        for (int p = 0; p < 2; p++) {
            if (p < npass) {
                uint32_t aaddr = sb + HHI + aoff(p * 64 + m0p + aRow, k0 * 2 + aK);
                uint32_t ah[4], al[4];
                ldm4(ah, aaddr);
                ldm4(al, aaddr + 65536);
                float* A0 = acc3[p];
                mma16816(A0, ah, bh);
                mma16816(A0, ah, bl);
                mma16816(A0, al, bh);
                mma16816(A0 + 4, ah, bh + 2);
                mma16816(A0 + 4, ah, bl + 2);
                mma16816(A0 + 4, al, bh + 2);
            }
        }
    }

    // ---- epilogue 3: + bias -> scatter ----
    {
        const float* bg = B3 + (size_t)e * 64;
        #pragma unroll
        for (int p = 0; p < 2; p++) {
            if (p < npass) {
                int r0 = p * 64 + m0p + (lane >> 2), r1 = r0 + 8;
                int n0g = (r0 < mrows) ? g_bucket[e * CAP + r0] : -1;
                int n1g = (r1 < mrows) ? g_bucket[e * CAP + r1] : -1;
                #pragma unroll
                for (int t = 0; t < 2; t++) {
                    int c0 = ch * 16 + t * 8 + (lane & 3) * 2;
                    float2 bv = *(const float2*)(bg + c0);
                    if (n0g >= 0) {
                        float2 o = make_float2(acc3[p][t * 4 + 0] + bv.x, acc3[p][t * 4 + 1] + bv.y);
                        *(float2*)(Og + (size_t)n0g * 64 + c0) = o;
                    }
                    if (n1g >= 0) {
                        float2 o = make_float2(acc3[p][t * 4 + 2] + bv.x, acc3[p][t * 4 + 3] + bv.y);
                        *(float2*)(Og + (size_t)n1g * 64 + c0) = o;
                    }
                }
            }
        }
    }
}

// ---------------- launch ----------------
extern "C" void kernel_launch(void* const* d_in, const int* in_sizes, int n_in,
                              void* d_out, int out_size) {
    const float* x  = (const float*)d_in[0];
    const int*   ind = (const int*)d_in[1];
    const float* W1 = (const float*)d_in[2];
    const float* b1 = (const float*)d_in[3];
    const float* W2 = (const float*)d_in[4];
    const float* b2 = (const float*)d_in[5];
    const float* Wl = (const float*)d_in[6];
    const float* bl = (const float*)d_in[7];
    float* out = (float*)d_out;

    (void)in_sizes; (void)n_in; (void)out_size;

    cudaFuncSetAttribute(k_mlp, cudaFuncAttributeMaxDynamicSharedMemorySize, SMEM_TOTAL);

    void* cnt_ptr = nullptr;
    cudaGetSymbolAddress(&cnt_ptr, g_cnt);
    cudaMemsetAsync(cnt_ptr, 0, NEXP * sizeof(int));

    k_fill<<<N_ROWS / 256, 256>>>(ind);
    k_mlp<<<NEXP, THREADS, SMEM_TOTAL>>>(x, W1, b1, W2, b2, Wl, bl, out);
}